// round 11
// baseline (speedup 1.0000x reference)
#include <cuda_runtime.h>
#include <math_constants.h>

// Scratch + sync state (zero-init at load; last-retiring block resets for
// graph replays). No dynamic allocation anywhere.
__device__ float g_P4[2 * 256];          // maxpool16(x4)  [b, hw]
__device__ float g_T3[2 * 256 * 256];    // maxpool8(x3)   [b, j, hw]
__device__ int   g_t3flag[512];          // per-plane ready flag [b*256+j]
__device__ int   g_p4cnt[2];             // per-batch P4 values done (==256)
__device__ int   g_finish = 0;           // retired blocks (for replay reset)

#define N_MAIN 8192

// ---------------------------------------------------------------------------
// Single kernel, grid = 8192 x 256. Block (b,k), b = bid>>12, k = bid&4095.
// WRITER blocks (k < 256, j = k):
//   1) x4 16x16 window -> P4[b,j]; fence; p4cnt[b]++        (1 KB read)
//   2) maxpool8 of x3 plane (b,j) -> g_T3; fence; flag=1    (64 KB read)
//   3) fall through to their own main unit (T3 vals kept in registers).
// ALL blocks (main unit):
//   prefetch x2 pool4 + x1 pool2 (4 aliases) + ff (8 planes) into registers,
//   t0 polls ONLY plane flag (b, k&255) (non-writers) + p4cnt[b]==256,
//   combine with T3/P4, stores only after the wait.
// Deadlock-free: every waiter's bid > its writers' bids; in-order dispatch.
// ---------------------------------------------------------------------------
__global__ void __launch_bounds__(256) fused_all_kernel(
        const float* __restrict__ x1, const float* __restrict__ x2,
        const float* __restrict__ x3, const float* __restrict__ x4,
        const float* __restrict__ ff, float* __restrict__ out) {
    const int bid = blockIdx.x;
    const int t   = threadIdx.x;
    const int b   = bid >> 12;
    const int k   = bid & 4095;
    const int oh  = t >> 4, ow = t & 15;
    const bool writer = (k < 256);

    float t3val;                             // this thread's T3[plane, t]
    if (writer) {
        const int j = k;
        // ---- phase 1: x4 window -> P4[b, j] (fast, unblocks p4cnt early) ----
        const float xv = x4[(size_t)b * 65536
                            + (16 * (j >> 4) + (t >> 4)) * 256
                            + 16 * (j & 15) + (t & 15)];
        __shared__ float red[8];
        float v = xv;
#pragma unroll
        for (int s = 16; s > 0; s >>= 1)
            v = fmaxf(v, __shfl_down_sync(0xFFFFFFFFu, v, s));
        if ((t & 31) == 0) red[t >> 5] = v;
        __syncthreads();
        if (t == 0) {
            float pm = red[0];
#pragma unroll
            for (int w = 1; w < 8; ++w) pm = fmaxf(pm, red[w]);
            g_P4[b * 256 + j] = pm;
            __threadfence();
            atomicAdd(&g_p4cnt[b], 1);
        }

        // ---- phase 2: maxpool8 of x3 plane (b, j) -> T3 + flag ----
        const float* base = x3 + ((size_t)b * 256 + j) * 16384;
        float m = -CUDART_INF_F;
#pragma unroll
        for (int r = 0; r < 8; ++r) {
            const float4* row = (const float4*)(base + (8 * oh + r) * 128 + 8 * ow);
            float4 v0 = row[0];
            float4 v1 = row[1];
            m = fmaxf(m, fmaxf(fmaxf(v0.x, v0.y), fmaxf(v0.z, v0.w)));
            m = fmaxf(m, fmaxf(fmaxf(v1.x, v1.y), fmaxf(v1.z, v1.w)));
        }
        t3val = m;
        g_T3[((size_t)b * 256 + j) * 256 + t] = m;
        __syncthreads();                     // all plane writes done
        if (t == 0) {
            __threadfence();                 // release plane
            *(volatile int*)&g_t3flag[b * 256 + j] = 1;
        }
    }

    // ================= main unit (every block) =================
    // ---- prologue-independent HBM reads: x2 pool4 ----
    const float* x2p = x2 + ((size_t)b * 4096 + k) * 4096;
    float p2 = -CUDART_INF_F;
#pragma unroll
    for (int r = 0; r < 4; ++r) {
        float4 v = *(const float4*)(x2p + (4 * oh + r) * 64 + 4 * ow);
        p2 = fmaxf(p2, fmaxf(fmaxf(v.x, v.y), fmaxf(v.z, v.w)));
    }

    // ---- prologue-independent HBM reads: x1 pool2 (4 aliases) ----
    float p1v[4];
#pragma unroll
    for (int m = 0; m < 4; ++m) {
        const int c = k + 4096 * m;
        const float* x1p = x1 + ((size_t)b * 16384 + c) * 1024;
        float2 a0 = *(const float2*)(x1p + (2 * oh)     * 32 + 2 * ow);
        float2 a1 = *(const float2*)(x1p + (2 * oh + 1) * 32 + 2 * ow);
        p1v[m] = fmaxf(fmaxf(a0.x, a0.y), fmaxf(a1.x, a1.y));
    }

    // ---- prologue-independent HBM reads: ff (both tile halves) ----
    const size_t obase = ((size_t)b * 32768 + k) * 256 + t;
    float f0[4], f1[4];
#pragma unroll
    for (int m = 0; m < 4; ++m) {
        const size_t o0 = obase + (size_t)(4096 * m) * 256;
        f0[m] = ff[o0];
        f1[m] = ff[o0 + (size_t)16384 * 256];
    }

    // ---- fine-grained wait ----
    const int plane = (b << 8) | (k & 255);
    if (t == 0) {
        if (!writer) {
            while (*(volatile int*)&g_t3flag[plane] == 0) __nanosleep(128);
        }
        while (*(volatile int*)&g_p4cnt[b] < 256) __nanosleep(128);
        __threadfence();                     // acquire
    }
    __syncthreads();                         // block-wide release of the wait
    if (!writer)
        t3val = g_T3[((size_t)plane) * 256 + t];

    const float basev = p2 + t3val + g_P4[b * 256 + t];

    // ---- stores only (all reads already in registers) ----
#pragma unroll
    for (int m = 0; m < 4; ++m) {
        const float s = basev + p1v[m];
        const size_t o0 = obase + (size_t)(4096 * m) * 256;
        out[o0]                       = fmaxf(s + f0[m], 0.0f);
        out[o0 + (size_t)16384 * 256] = fmaxf(s + f1[m], 0.0f);
    }

    // ---- replay-safe reset: last-retiring block clears all sync state ----
    __shared__ int is_last;
    __syncthreads();
    if (t == 0) {
        const int old = atomicAdd(&g_finish, 1);
        is_last = (old == N_MAIN - 1);
    }
    __syncthreads();
    if (is_last) {
        g_t3flag[t]       = 0;
        g_t3flag[t + 256] = 0;
        if (t < 2) g_p4cnt[t] = 0;
        if (t == 0) {
            g_finish = 0;
            __threadfence();
        }
    }
}

// ---------------------------------------------------------------------------
// Launch: inputs in metadata order: x1, x2, x3, x4, pure_ff
// ---------------------------------------------------------------------------
extern "C" void kernel_launch(void* const* d_in, const int* in_sizes, int n_in,
                              void* d_out, int out_size) {
    const float* x1 = (const float*)d_in[0];
    const float* x2 = (const float*)d_in[1];
    const float* x3 = (const float*)d_in[2];
    const float* x4 = (const float*)d_in[3];
    const float* ff = (const float*)d_in[4];
    float* out = (float*)d_out;

    fused_all_kernel<<<N_MAIN, 256>>>(x1, x2, x3, x4, ff, out);
}

// round 12
// speedup vs baseline: 1.1198x; 1.1198x over previous
#include <cuda_runtime.h>
#include <math_constants.h>

// Scratch + sync state (no dynamic allocation allowed).
__device__ float g_P4[2 * 256];          // maxpool16(x4)  [b, hw]
__device__ float g_T3[2 * 256 * 256];    // maxpool8(x3)   [b, j, hw]
__device__ int   g_done   = 0;           // prologue blocks completed
__device__ int   g_finish = 0;           // blocks completed (for replay reset)

#define N_PRO   1024                      // prologue blocks (half x3 plane each)
#define N_MAIN  8192                      // main blocks
#define N_TOTAL (N_PRO + N_MAIN)

// ---------------------------------------------------------------------------
// Single fused kernel, grid = 9216 x 256 (R10 skeleton, denser prologue).
//   bid [0, 1024): prologue block: half of x3 plane p = bid>>1 (q = bid&1),
//       32 KB read, 2 threads per output window; blocks 0..511 ALSO pool one
//       x4 16x16 window -> P4 (x4 load issued first). One atomicAdd(g_done)
//       per block when BOTH parts are done -> g_done==1024 releases everyone.
//   bid [1024, 9216): main block (b, k): prefetch ALL prologue-independent
//       reads (x2 pool4, x1 pool2 x4 aliases, ff both halves) into registers,
//       t0-only spin on g_done==N_PRO, combine with T3/P4, stores only after.
// Deadlock-free at any occupancy: prologue bids precede all main bids in the
// in-order dispatcher and prologue blocks never wait.
// Last finishing block resets counters so graph replays start clean.
// ---------------------------------------------------------------------------
__global__ void __launch_bounds__(256) fused_all_kernel(
        const float* __restrict__ x1, const float* __restrict__ x2,
        const float* __restrict__ x3, const float* __restrict__ x4,
        const float* __restrict__ ff, float* __restrict__ out) {
    const int bid = blockIdx.x;
    const int t   = threadIdx.x;

    if (bid < N_PRO) {
        // ================= prologue block =================
        const bool hasP4 = (bid < 512);
        float xv = 0.0f;
        if (hasP4) {
            // ---- x4 window for P4 value 'bid' (issued first, tiny) ----
            const int xb = bid >> 8, pix = bid & 255;
            xv = x4[(size_t)xb * 65536
                    + (16 * (pix >> 4) + (t >> 4)) * 256
                    + 16 * (pix & 15) + (t & 15)];
        }

        // ---- half of x3 plane p = bid>>1 : rows q*64..q*64+63 ----
        const int p  = bid >> 1;             // plane index [0,512) = b*256+j
        const int q  = bid & 1;              // which half
        const int sub = t & 1;               // 2 threads per output window
        const int o   = t >> 1;              // [0,128) local output
        const int ohl = o >> 4;              // [0,8) local output row
        const int ow2 = o & 15;              // [0,16) output col
        const float* base = x3 + (size_t)p * 16384;
        const int row0 = 8 * (q * 8 + ohl) + sub * 4;   // this thread's 4 rows
        float m = -CUDART_INF_F;
#pragma unroll
        for (int r = 0; r < 4; ++r) {
            const float4* row = (const float4*)(base + (row0 + r) * 128 + 8 * ow2);
            float4 v0 = row[0];
            float4 v1 = row[1];
            m = fmaxf(m, fmaxf(fmaxf(v0.x, v0.y), fmaxf(v0.z, v0.w)));
            m = fmaxf(m, fmaxf(fmaxf(v1.x, v1.y), fmaxf(v1.z, v1.w)));
        }
        m = fmaxf(m, __shfl_xor_sync(0xFFFFFFFFu, m, 1));
        if (sub == 0)
            g_T3[(size_t)p * 256 + (q * 8 + ohl) * 16 + ow2] = m;

        if (hasP4) {
            // ---- reduce x4 window to one value ----
            __shared__ float red[8];
            float v = xv;
#pragma unroll
            for (int s = 16; s > 0; s >>= 1)
                v = fmaxf(v, __shfl_down_sync(0xFFFFFFFFu, v, s));
            if ((t & 31) == 0) red[t >> 5] = v;
            __syncthreads();
            if (t == 0) {
                float pm = red[0];
#pragma unroll
                for (int w = 1; w < 8; ++w) pm = fmaxf(pm, red[w]);
                g_P4[bid] = pm;
            }
        }

        // Release: this block's T3 (and P4) writes become visible, then count.
        __syncthreads();
        if (t == 0) {
            __threadfence();
            atomicAdd(&g_done, 1);
        }
    } else {
        // ================= main block =================
        const int B  = bid - N_PRO;            // [0, 8192)
        const int b  = B >> 12, k = B & 4095;
        const int oh = t >> 4, ow = t & 15;

        // ---- prologue-independent HBM reads: x2 pool4 ----
        const float* x2p = x2 + ((size_t)b * 4096 + k) * 4096;
        float p2 = -CUDART_INF_F;
#pragma unroll
        for (int r = 0; r < 4; ++r) {
            float4 v = *(const float4*)(x2p + (4 * oh + r) * 64 + 4 * ow);
            p2 = fmaxf(p2, fmaxf(fmaxf(v.x, v.y), fmaxf(v.z, v.w)));
        }

        // ---- prologue-independent HBM reads: x1 pool2 (4 aliases) ----
        float p1v[4];
#pragma unroll
        for (int m = 0; m < 4; ++m) {
            const int c = k + 4096 * m;
            const float* x1p = x1 + ((size_t)b * 16384 + c) * 1024;
            float2 a0 = *(const float2*)(x1p + (2 * oh)     * 32 + 2 * ow);
            float2 a1 = *(const float2*)(x1p + (2 * oh + 1) * 32 + 2 * ow);
            p1v[m] = fmaxf(fmaxf(a0.x, a0.y), fmaxf(a1.x, a1.y));
        }

        // ---- prologue-independent HBM reads: ff (both tile halves) ----
        const size_t obase = ((size_t)b * 32768 + k) * 256 + t;
        float f0[4], f1[4];
#pragma unroll
        for (int m = 0; m < 4; ++m) {
            const size_t o0 = obase + (size_t)(4096 * m) * 256;
            f0[m] = ff[o0];
            f1[m] = ff[o0 + (size_t)16384 * 256];
        }

        // ---- wait for prologue: ONLY t==0 polls (no L2 spin-storm) ----
        if (t == 0) {
            if (*(volatile int*)&g_done < N_PRO) {
                while (*(volatile int*)&g_done < N_PRO) __nanosleep(256);
            }
            __threadfence();                   // acquire side
        }
        __syncthreads();                       // block-wide release of the wait

        const float basev = p2
                          + g_T3[((size_t)b * 256 + (k & 255)) * 256 + t]
                          + g_P4[b * 256 + t];

        // ---- stores only (all reads already in registers) ----
#pragma unroll
        for (int m = 0; m < 4; ++m) {
            const float s = basev + p1v[m];
            const size_t o0 = obase + (size_t)(4096 * m) * 256;
            out[o0]                       = fmaxf(s + f0[m], 0.0f);
            out[o0 + (size_t)16384 * 256] = fmaxf(s + f1[m], 0.0f);
        }
    }

    // ---- replay-safe counter reset: last block of the grid cleans up ----
    __syncthreads();
    if (t == 0) {
        const int old = atomicAdd(&g_finish, 1);
        if (old == N_TOTAL - 1) {
            g_done   = 0;
            g_finish = 0;
            __threadfence();
        }
    }
}

// ---------------------------------------------------------------------------
// Launch: inputs in metadata order: x1, x2, x3, x4, pure_ff
// ---------------------------------------------------------------------------
extern "C" void kernel_launch(void* const* d_in, const int* in_sizes, int n_in,
                              void* d_out, int out_size) {
    const float* x1 = (const float*)d_in[0];
    const float* x2 = (const float*)d_in[1];
    const float* x3 = (const float*)d_in[2];
    const float* x4 = (const float*)d_in[3];
    const float* ff = (const float*)d_in[4];
    float* out = (float*)d_out;

    fused_all_kernel<<<N_TOTAL, 256>>>(x1, x2, x3, x4, ff, out);
}

// round 13
// speedup vs baseline: 1.1204x; 1.0005x over previous
#include <cuda_runtime.h>
#include <math_constants.h>

// Scratch + sync state (no dynamic allocation allowed).
__device__ float g_P4[2 * 256];          // maxpool16(x4)  [b, hw]
__device__ float g_T3[2 * 256 * 256];    // maxpool8(x3)   [b, j, hw]
__device__ int   g_done   = 0;           // prologue blocks completed
__device__ int   g_finish = 0;           // blocks completed (for replay reset)

#define N_PRO   1024                      // prologue blocks (half x3 plane each)
#define N_MAIN  8192                      // main blocks
#define N_TOTAL (N_PRO + N_MAIN)

// ---------------------------------------------------------------------------
// Single fused kernel, grid = 9216 x 256 (R12 skeleton + float4 x1 loads).
//   bid [0, 1024): prologue: half of x3 plane p = bid>>1 (q = bid&1); blocks
//       0..511 also pool one x4 16x16 window -> P4. atomicAdd(g_done) when done.
//   bid [1024, 9216): main block (b, k): prefetch ALL prologue-independent
//       reads (x2 pool4, x1 pool2 via LDG.128 + shfl pair-exchange, ff both
//       halves) into registers, t0-only spin on g_done==N_PRO, combine with
//       T3/P4, stores only after the wait.
// Deadlock-free at any occupancy: prologue bids precede all main bids in the
// in-order dispatcher and prologue blocks never wait.
// ---------------------------------------------------------------------------
__global__ void __launch_bounds__(256) fused_all_kernel(
        const float* __restrict__ x1, const float* __restrict__ x2,
        const float* __restrict__ x3, const float* __restrict__ x4,
        const float* __restrict__ ff, float* __restrict__ out) {
    const int bid = blockIdx.x;
    const int t   = threadIdx.x;

    if (bid < N_PRO) {
        // ================= prologue block =================
        const bool hasP4 = (bid < 512);
        float xv = 0.0f;
        if (hasP4) {
            const int xb = bid >> 8, pix = bid & 255;
            xv = x4[(size_t)xb * 65536
                    + (16 * (pix >> 4) + (t >> 4)) * 256
                    + 16 * (pix & 15) + (t & 15)];
        }

        // ---- half of x3 plane p = bid>>1 : rows q*64..q*64+63 ----
        const int p   = bid >> 1;
        const int q   = bid & 1;
        const int sub = t & 1;
        const int o   = t >> 1;
        const int ohl = o >> 4;
        const int ow2 = o & 15;
        const float* base = x3 + (size_t)p * 16384;
        const int row0 = 8 * (q * 8 + ohl) + sub * 4;
        float m = -CUDART_INF_F;
#pragma unroll
        for (int r = 0; r < 4; ++r) {
            const float4* row = (const float4*)(base + (row0 + r) * 128 + 8 * ow2);
            float4 v0 = row[0];
            float4 v1 = row[1];
            m = fmaxf(m, fmaxf(fmaxf(v0.x, v0.y), fmaxf(v0.z, v0.w)));
            m = fmaxf(m, fmaxf(fmaxf(v1.x, v1.y), fmaxf(v1.z, v1.w)));
        }
        m = fmaxf(m, __shfl_xor_sync(0xFFFFFFFFu, m, 1));
        if (sub == 0)
            g_T3[(size_t)p * 256 + (q * 8 + ohl) * 16 + ow2] = m;

        if (hasP4) {
            __shared__ float red[8];
            float v = xv;
#pragma unroll
            for (int s = 16; s > 0; s >>= 1)
                v = fmaxf(v, __shfl_down_sync(0xFFFFFFFFu, v, s));
            if ((t & 31) == 0) red[t >> 5] = v;
            __syncthreads();
            if (t == 0) {
                float pm = red[0];
#pragma unroll
                for (int w = 1; w < 8; ++w) pm = fmaxf(pm, red[w]);
                g_P4[bid] = pm;
            }
        }

        __syncthreads();
        if (t == 0) {
            __threadfence();
            atomicAdd(&g_done, 1);
        }
    } else {
        // ================= main block =================
        const int B  = bid - N_PRO;            // [0, 8192)
        const int b  = B >> 12, k = B & 4095;
        const int oh = t >> 4, ow = t & 15;

        // ---- prologue-independent HBM reads: x2 pool4 (LDG.128) ----
        const float* x2p = x2 + ((size_t)b * 4096 + k) * 4096;
        float p2 = -CUDART_INF_F;
#pragma unroll
        for (int r = 0; r < 4; ++r) {
            float4 v = *(const float4*)(x2p + (4 * oh + r) * 64 + 4 * ow);
            p2 = fmaxf(p2, fmaxf(fmaxf(v.x, v.y), fmaxf(v.z, v.w)));
        }

        // ---- x1 pool2 via LDG.128 pair-load + shfl exchange ----
        // Thread pair (t&~1, t|1) shares one float4 per row: even lane loads
        // row 2*oh, odd lane loads row 2*oh+1, covering BOTH pixels' windows
        // (cols 4*ow2..4*ow2+3). One shfl_xor(1) swaps the cross-row halves.
        const int odd  = t & 1;
        const int ow2p = ow >> 1;              // pair base (ow/2)
        float p1v[4];
#pragma unroll
        for (int m = 0; m < 4; ++m) {
            const int c = k + 4096 * m;
            const float* x1p = x1 + ((size_t)b * 16384 + c) * 1024;
            float4 v = *(const float4*)(x1p + (2 * oh + odd) * 32 + 4 * ow2p);
            const float a  = fmaxf(v.x, v.y);  // even pixel, my row
            const float bq = fmaxf(v.z, v.w);  // odd pixel, my row
            const float send = odd ? a : bq;   // what my partner needs
            const float recv = __shfl_xor_sync(0xFFFFFFFFu, send, 1);
            p1v[m] = fmaxf(odd ? bq : a, recv);
        }

        // ---- prologue-independent HBM reads: ff (both tile halves) ----
        const size_t obase = ((size_t)b * 32768 + k) * 256 + t;
        float f0[4], f1[4];
#pragma unroll
        for (int m = 0; m < 4; ++m) {
            const size_t o0 = obase + (size_t)(4096 * m) * 256;
            f0[m] = ff[o0];
            f1[m] = ff[o0 + (size_t)16384 * 256];
        }

        // ---- wait for prologue: ONLY t==0 polls ----
        if (t == 0) {
            if (*(volatile int*)&g_done < N_PRO) {
                while (*(volatile int*)&g_done < N_PRO) __nanosleep(256);
            }
            __threadfence();                   // acquire side
        }
        __syncthreads();                       // block-wide release of the wait

        const float basev = p2
                          + g_T3[((size_t)b * 256 + (k & 255)) * 256 + t]
                          + g_P4[b * 256 + t];

        // ---- stores only (all reads already in registers) ----
#pragma unroll
        for (int m = 0; m < 4; ++m) {
            const float s = basev + p1v[m];
            const size_t o0 = obase + (size_t)(4096 * m) * 256;
            out[o0]                       = fmaxf(s + f0[m], 0.0f);
            out[o0 + (size_t)16384 * 256] = fmaxf(s + f1[m], 0.0f);
        }
    }

    // ---- replay-safe counter reset: last block of the grid cleans up ----
    __syncthreads();
    if (t == 0) {
        const int old = atomicAdd(&g_finish, 1);
        if (old == N_TOTAL - 1) {
            g_done   = 0;
            g_finish = 0;
            __threadfence();
        }
    }
}

// ---------------------------------------------------------------------------
// Launch: inputs in metadata order: x1, x2, x3, x4, pure_ff
// ---------------------------------------------------------------------------
extern "C" void kernel_launch(void* const* d_in, const int* in_sizes, int n_in,
                              void* d_out, int out_size) {
    const float* x1 = (const float*)d_in[0];
    const float* x2 = (const float*)d_in[1];
    const float* x3 = (const float*)d_in[2];
    const float* x4 = (const float*)d_in[3];
    const float* ff = (const float*)d_in[4];
    float* out = (float*)d_out;

    fused_all_kernel<<<N_TOTAL, 256>>>(x1, x2, x3, x4, ff, out);
}